// round 3
// baseline (speedup 1.0000x reference)
#include <cuda_runtime.h>
#include <cstdint>
#include <cmath>

#define BB 512
#define NN 1000
#define CC 50
#define EE 128
#define HH 8
#define DD 16
#define SPLIT 8
#define NPS (NN/SPLIT)
#define NEGV (-1e9f)

// scratch (no cudaMalloc allowed)
__device__ float g_part[BB*SPLIT*2*EE];   // partial sums: [b][split][{mask, mask|cmask}][e]
__device__ float g_Wqf[3*EE*EE];          // Wq @ mha_Wq   (384 x 128)
__device__ float g_Wkf[EE*EE];            // Wk @ mha_Wk
__device__ float g_Wvf[EE*EE];            // Wv @ mha_Wv

// ---------------------------------------------------------------------------
// Kernel 0: fuse projection weights (batch-independent)
// ---------------------------------------------------------------------------
__global__ void k_fuse(const float* __restrict__ Wq, const float* __restrict__ Wk,
                       const float* __restrict__ Wv, const float* __restrict__ mWq,
                       const float* __restrict__ mWk, const float* __restrict__ mWv) {
    int r = blockIdx.x, t = threadIdx.x;
    if (r < 3*EE) {
        float a = 0.f;
        #pragma unroll 8
        for (int e = 0; e < EE; e++) a += Wq[r*EE + e] * mWq[e*EE + t];
        g_Wqf[r*EE + t] = a;
    } else if (r < 3*EE + EE) {
        int e0 = r - 3*EE;
        float a = 0.f;
        #pragma unroll 8
        for (int x = 0; x < EE; x++) a += Wk[e0*EE + x] * mWk[x*EE + t];
        g_Wkf[e0*EE + t] = a;
    } else {
        int e0 = r - 4*EE;
        float a = 0.f;
        #pragma unroll 8
        for (int x = 0; x < EE; x++) a += Wv[e0*EE + x] * mWv[x*EE + t];
        g_Wvf[e0*EE + t] = a;
    }
}

// ---------------------------------------------------------------------------
// Kernel 1: masked reduction over node_embeddings (the 262 MB read)
// grid (B, SPLIT), 128 threads; thread t owns embedding dim t. Coalesced rows.
// Bool inputs arrive as int32.
// ---------------------------------------------------------------------------
__global__ void __launch_bounds__(128) k_reduce(const float* __restrict__ nodes,
                                                const int* __restrict__ mask,
                                                const int* __restrict__ cmask) {
    int b = blockIdx.x, s = blockIdx.y, t = threadIdx.x;
    __shared__ uint8_t sM[NPS], sC[NPS];
    const int* m  = mask  + b*NN + s*NPS;
    const int* cm = cmask + b*NN + s*NPS;
    if (t < NPS) { sM[t] = (uint8_t)(m[t] != 0); sC[t] = (uint8_t)(cm[t] != 0); }
    __syncthreads();

    const float* base = nodes + ((size_t)b*NN + (size_t)s*NPS)*EE + t;
    float a0 = 0.f, a1 = 0.f;
    #pragma unroll 5
    for (int i = 0; i < NPS; i++) {
        float v  = __ldg(base + (size_t)i*EE);
        float k0 = sM[i] ? 0.f : v;      // unvisit_mean: keep where mask==False
        a0 += k0;
        a1 += sC[i] ? 0.f : k0;          // unvisit_cluster: keep where (mask|cmask)==False
    }
    int idx = (b*SPLIT + s)*2*EE + t;
    g_part[idx]      = a0;
    g_part[idx + EE] = a1;
}

// ---------------------------------------------------------------------------
// Kernel 2: everything else, one block per batch element
// ---------------------------------------------------------------------------
__global__ void __launch_bounds__(128) k_main(
    const float* __restrict__ depot, const float* __restrict__ CE,
    const float* __restrict__ cur,   const float* __restrict__ augc,
    const float* __restrict__ gein,  const float* __restrict__ Wks,
    const float* __restrict__ Wo,
    const int* __restrict__ isnew, const int* __restrict__ vcm_g,
    const int* __restrict__ guid_in, float* __restrict__ out)
{
    int b = blockIdx.x, t = threadIdx.x;
    __shared__ float sCE[CC*EE];
    __shared__ float sCtx[3*EE];
    __shared__ float sUC[EE];
    __shared__ float sQ[EE];
    __shared__ float sKQ[HH*EE];
    __shared__ float sSc[HH*CC];
    __shared__ float sAt[HH*CC];
    __shared__ float sAce[HH*EE];
    __shared__ float sGl[EE];
    __shared__ float sOut[EE];
    __shared__ float sW2[EE];
    __shared__ float sLg[CC];
    __shared__ int   sVcm[CC];
    __shared__ float sMax, sLse;
    __shared__ int   sArg;

    // load cluster embeddings (50x128) into smem, vectorized
    {
        const float4* src = (const float4*)(CE + (size_t)b*CC*EE);
        float4* dst = (float4*)sCE;
        #pragma unroll
        for (int i = t; i < CC*EE/4; i += 128) dst[i] = src[i];
    }

    // combine reduction partials
    float um = 0.f, uc = 0.f;
    #pragma unroll
    for (int s = 0; s < SPLIT; s++) {
        int idx = (b*SPLIT + s)*2*EE + t;
        um += g_part[idx];
        uc += g_part[idx + EE];
    }
    um *= (1.f/NN); uc *= (1.f/NN);
    sCtx[t]        = um;
    sCtx[EE + t]   = cur[b*EE + t];
    sCtx[2*EE + t] = depot[b*EE + t];
    sUC[t] = uc;
    if (t < CC) sVcm[t] = (vcm_g[b*CC + t] != 0);
    __syncthreads();

    // vcm[0] = !all(vcm[1:]) (single writer between syncs; read after later sync)
    if (t == 0) {
        int all = 1;
        for (int c = 1; c < CC; c++) all &= (sVcm[c] != 0);
        sVcm[0] = !all;
    }

    // qvec (already head-projected via fused Wqf): 384 MACs/thread
    {
        float a = 0.f;
        #pragma unroll 8
        for (int i = 0; i < 3*EE; i++) a += sCtx[i] * g_Wqf[i*EE + t];
        sQ[t] = a;
    }
    __syncthreads();

    // kq[h][e=t] = sum_d q[h*16+d] * Wkf[e, h*16+d]
    {
        const float* wrow = g_Wkf + t*EE;
        #pragma unroll
        for (int h = 0; h < HH; h++) {
            float a = 0.f;
            #pragma unroll
            for (int d = 0; d < DD; d++) a += sQ[h*DD + d] * wrow[h*DD + d];
            sKQ[h*EE + t] = a;
        }
    }
    __syncthreads();

    // scores[h][c] = 0.25 * CE[c] . kq[h], mask -> NEG
    for (int idx = t; idx < HH*CC; idx += 128) {
        int h = idx / CC, c = idx % CC;
        float a = 0.f;
        #pragma unroll 8
        for (int e = 0; e < EE; e++) a += sCE[c*EE + e] * sKQ[h*EE + e];
        a *= 0.25f;                    // 1/sqrt(D), D=16
        if (sVcm[c]) a = NEGV;
        sSc[h*CC + c] = a;
    }
    __syncthreads();

    // softmax per head (8 threads, 50 elems each)
    if (t < HH) {
        float mx = -3e38f;
        for (int c = 0; c < CC; c++) mx = fmaxf(mx, sSc[t*CC + c]);
        float sm = 0.f;
        for (int c = 0; c < CC; c++) { float e = expf(sSc[t*CC + c] - mx); sAt[t*CC + c] = e; sm += e; }
        float inv = 1.f / sm;
        for (int c = 0; c < CC; c++) sAt[t*CC + c] *= inv;
    }
    __syncthreads();

    // a_ce[h][e=t] = sum_c attn[h][c] * CE[c][e]
    #pragma unroll
    for (int h = 0; h < HH; h++) {
        float a = 0.f;
        for (int c = 0; c < CC; c++) a += sAt[h*CC + c] * sCE[c*EE + t];
        sAce[h*EE + t] = a;
    }
    __syncthreads();

    // glimpse_flat[j=t] = a_ce[h] . Wvf[:, j]   (h = j/16)
    {
        int h = t / DD;
        float a = 0.f;
        #pragma unroll 8
        for (int e = 0; e < EE; e++) a += sAce[h*EE + e] * g_Wvf[e*EE + t];
        sGl[t] = a;
    }
    __syncthreads();

    // out = glimpse @ Wo
    {
        float a = 0.f;
        #pragma unroll 8
        for (int j = 0; j < EE; j++) a += sGl[j] * Wo[j*EE + t];
        sOut[t] = a;
    }
    __syncthreads();

    // w2[e=t] = Wks[e,:] . out
    {
        const float* wr = Wks + t*EE;
        float a = 0.f;
        #pragma unroll 8
        for (int f = 0; f < EE; f++) a += wr[f] * sOut[f];
        sW2[t] = a;
    }
    __syncthreads();

    // logit[c] = tanh(CE[c].w2 / sqrt(E)) * CLIP, mask -> NEG
    if (t < CC) {
        float a = 0.f;
        #pragma unroll 8
        for (int e = 0; e < EE; e++) a += sCE[t*EE + e] * sW2[e];
        a *= 0.08838834764831845f;     // 1/sqrt(128)
        a = tanhf(a) * 10.f;
        if (sVcm[t]) a = NEGV;
        sLg[t] = a;
    }
    __syncthreads();

    // argmax (first-index tie-break like jnp.argmax) + logsumexp
    if (t == 0) {
        float mx = sLg[0]; int arg = 0;
        for (int c = 1; c < CC; c++) if (sLg[c] > mx) { mx = sLg[c]; arg = c; }
        float sm = 0.f;
        for (int c = 0; c < CC; c++) sm += expf(sLg[c] - mx);
        sMax = mx; sLse = logf(sm); sArg = arg;
    }
    __syncthreads();

    int  guid = sArg;
    bool isn  = isnew[b] != 0;
    float ge  = sCE[guid*EE + t];      // new guidance embedding, dim t

    const size_t OFF1 = (size_t)BB*4*EE;            // guid_embed_out
    const size_t OFF2 = OFF1 + (size_t)BB*EE;       // guid_out
    const size_t OFF3 = OFF2 + BB;                  // clu_prob

    float* ao = out + (size_t)b*4*EE;
    const float* ac = augc + (size_t)b*4*EE;
    ao[t]         = isn ? sUC[t]         : ac[t];           // unvisit_cluster
    ao[EE + t]    = isn ? sCtx[EE + t]   : ac[EE + t];      // current
    ao[2*EE + t]  = isn ? ge             : ac[2*EE + t];    // new_guid_embed
    ao[3*EE + t]  = isn ? sCtx[2*EE + t] : ac[3*EE + t];    // depot

    out[OFF1 + (size_t)b*EE + t] = isn ? ge : gein[b*EE + t];
    if (t == 0) out[OFF2 + b] = (float)(isn ? guid : guid_in[b]);
    if (t < CC) out[OFF3 + (size_t)b*CC + t] = isn ? (sLg[t] - sMax - sLse) : 0.f;
}

// ---------------------------------------------------------------------------
extern "C" void kernel_launch(void* const* d_in, const int* in_sizes, int n_in,
                              void* d_out, int out_size) {
    const float* depot = (const float*)d_in[0];
    const float* CE    = (const float*)d_in[1];
    const float* cur   = (const float*)d_in[2];
    const float* nodes = (const float*)d_in[3];
    const float* augc  = (const float*)d_in[4];
    const float* gein  = (const float*)d_in[5];
    const float* Wq    = (const float*)d_in[6];
    const float* Wk    = (const float*)d_in[7];
    const float* Wv    = (const float*)d_in[8];
    const float* Wks   = (const float*)d_in[9];
    const float* mWq   = (const float*)d_in[10];
    const float* mWk   = (const float*)d_in[11];
    const float* mWv   = (const float*)d_in[12];
    const float* Wo    = (const float*)d_in[13];
    const int* isnew   = (const int*)d_in[14];   // bool -> int32
    const int* mask    = (const int*)d_in[15];   // bool -> int32
    const int* cmask   = (const int*)d_in[16];   // bool -> int32
    const int* vcm     = (const int*)d_in[17];   // bool -> int32
    const int* guid    = (const int*)d_in[18];
    // d_in[19] = step (unused)

    k_fuse<<<5*EE, 128>>>(Wq, Wk, Wv, mWq, mWk, mWv);
    dim3 gr(BB, SPLIT);
    k_reduce<<<gr, 128>>>(nodes, mask, cmask);
    k_main<<<BB, 128>>>(depot, CE, cur, augc, gein, Wks, Wo, isnew, vcm, guid,
                        (float*)d_out);
}

// round 5
// speedup vs baseline: 1.2153x; 1.2153x over previous
#include <cuda_runtime.h>
#include <cstdint>
#include <cmath>

#define BB 512
#define NN 1000
#define CC 50
#define EE 128
#define HH 8
#define DD 16
#define SPLIT 8
#define NPS (NN/SPLIT)
#define NEGV (-1e9f)
#define FUSE_ROWS (5*EE)          // 640 rows of weight fusion work

// scratch (no cudaMalloc allowed)
__device__ float g_part[BB*SPLIT*2*EE];   // [b][split][{mask, mask|cmask}][e]
__device__ float g_Wqf[3*EE*EE];          // Wq @ mha_Wq   (384 x 128)
__device__ float g_Wkf[EE*EE];            // Wk @ mha_Wk
__device__ float g_Wvf[EE*EE];            // Wv @ mha_Wv

// ---------------------------------------------------------------------------
// Kernel 1: masked reduction (skip masked rows) + weight fusion folded into
// the same grid so it overlaps instead of serializing.
// grid (BB, SPLIT+2), 128 threads.
//   y <  SPLIT : reduction plane s=y for batch b=blockIdx.x
//   y >= SPLIT : weight-fusion row fr = (y-SPLIT)*BB + blockIdx.x
// ---------------------------------------------------------------------------
__global__ void __launch_bounds__(128) k_pre(
    const float* __restrict__ nodes,
    const int* __restrict__ mask, const int* __restrict__ cmask,
    const float* __restrict__ Wq, const float* __restrict__ Wk,
    const float* __restrict__ Wv, const float* __restrict__ mWq,
    const float* __restrict__ mWk, const float* __restrict__ mWv)
{
    const int b = blockIdx.x, y = blockIdx.y, t = threadIdx.x;

    if (y >= SPLIT) {
        // ---- weight fusion plane ----
        int fr = (y - SPLIT)*BB + b;
        if (fr >= FUSE_ROWS) return;
        if (fr < 3*EE) {
            float a = 0.f;
            #pragma unroll 8
            for (int e = 0; e < EE; e++) a += Wq[fr*EE + e] * mWq[e*EE + t];
            g_Wqf[fr*EE + t] = a;
        } else if (fr < 4*EE) {
            int e0 = fr - 3*EE;
            float a = 0.f;
            #pragma unroll 8
            for (int x = 0; x < EE; x++) a += Wk[e0*EE + x] * mWk[x*EE + t];
            g_Wkf[e0*EE + t] = a;
        } else {
            int e0 = fr - 4*EE;
            float a = 0.f;
            #pragma unroll 8
            for (int x = 0; x < EE; x++) a += Wv[e0*EE + x] * mWv[x*EE + t];
            g_Wvf[e0*EE + t] = a;
        }
        return;
    }

    // ---- reduction plane: rows [y*NPS, (y+1)*NPS) of batch b ----
    __shared__ uint8_t sM[NPS], sC[NPS];
    __shared__ float4  sP0[4][32];   // native float4 -> guaranteed 16B alignment
    __shared__ float4  sP1[4][32];

    const int* m  = mask  + b*NN + y*NPS;
    const int* cm = cmask + b*NN + y*NPS;
    if (t < NPS) {
        sM[t] = (uint8_t)(m[t] != 0);
        sC[t] = (uint8_t)(cm[t] != 0);
    }
    __syncthreads();

    const int warp = t >> 5, lane = t & 31;
    // warp reads one full 512B row per float4 load (lane -> dims 4*lane..+3)
    const float4* base = (const float4*)(nodes + ((size_t)b*NN + (size_t)y*NPS)*EE);

    float4 a0 = make_float4(0.f,0.f,0.f,0.f);
    float4 a1 = make_float4(0.f,0.f,0.f,0.f);
    for (int r = warp; r < NPS; r += 4) {
        if (!sM[r]) {                           // warp-uniform: skip masked rows
            float4 v = __ldg(base + r*32 + lane);
            a0.x += v.x; a0.y += v.y; a0.z += v.z; a0.w += v.w;
            if (!sC[r]) { a1.x += v.x; a1.y += v.y; a1.z += v.z; a1.w += v.w; }
        }
    }
    sP0[warp][lane] = a0;
    sP1[warp][lane] = a1;
    __syncthreads();

    // thread t reduces scalar dim t across the 4 warps
    const float* p0 = (const float*)sP0;
    const float* p1 = (const float*)sP1;
    float s0 = p0[t] + p0[128 + t] + p0[256 + t] + p0[384 + t];
    float s1 = p1[t] + p1[128 + t] + p1[256 + t] + p1[384 + t];
    int idx = (b*SPLIT + y)*2*EE + t;
    g_part[idx]      = s0;
    g_part[idx + EE] = s1;
}

// ---------------------------------------------------------------------------
// Kernel 2: everything else, one block per batch element
// ---------------------------------------------------------------------------
__global__ void __launch_bounds__(128) k_main(
    const float* __restrict__ depot, const float* __restrict__ CE,
    const float* __restrict__ cur,   const float* __restrict__ augc,
    const float* __restrict__ gein,  const float* __restrict__ Wks,
    const float* __restrict__ Wo,
    const int* __restrict__ isnew, const int* __restrict__ vcm_g,
    const int* __restrict__ guid_in, float* __restrict__ out)
{
    int b = blockIdx.x, t = threadIdx.x;
    __shared__ __align__(16) float sCE[CC*EE];
    __shared__ float sCtx[3*EE];
    __shared__ float sUC[EE];
    __shared__ float sQ[EE];
    __shared__ float sKQ[HH*EE];
    __shared__ float sSc[HH*CC];
    __shared__ float sAt[HH*CC];
    __shared__ float sAce[HH*EE];
    __shared__ float sGl[EE];
    __shared__ float sOut[EE];
    __shared__ float sW2[EE];
    __shared__ float sLg[CC];
    __shared__ int   sVcm[CC];
    __shared__ float sMax, sLse;
    __shared__ int   sArg;

    // load cluster embeddings (50x128) into smem, vectorized
    {
        const float4* src = (const float4*)(CE + (size_t)b*CC*EE);
        float4* dst = (float4*)sCE;
        #pragma unroll
        for (int i = t; i < CC*EE/4; i += 128) dst[i] = src[i];
    }

    // combine reduction partials
    float um = 0.f, uc = 0.f;
    #pragma unroll
    for (int s = 0; s < SPLIT; s++) {
        int idx = (b*SPLIT + s)*2*EE + t;
        um += g_part[idx];
        uc += g_part[idx + EE];
    }
    um *= (1.f/NN); uc *= (1.f/NN);
    sCtx[t]        = um;
    sCtx[EE + t]   = cur[b*EE + t];
    sCtx[2*EE + t] = depot[b*EE + t];
    sUC[t] = uc;
    if (t < CC) sVcm[t] = (vcm_g[b*CC + t] != 0);
    __syncthreads();

    // vcm[0] = !all(vcm[1:]) (single writer; consumed after a later sync)
    if (t == 0) {
        int all = 1;
        for (int c = 1; c < CC; c++) all &= (sVcm[c] != 0);
        sVcm[0] = !all;
    }

    // q (head-projected via fused Wqf): 384 MACs/thread
    {
        float a = 0.f;
        #pragma unroll 8
        for (int i = 0; i < 3*EE; i++) a += sCtx[i] * g_Wqf[i*EE + t];
        sQ[t] = a;
    }
    __syncthreads();

    // kq[h][e=t] = sum_d q[h*16+d] * Wkf[e, h*16+d]
    {
        const float* wrow = g_Wkf + t*EE;
        #pragma unroll
        for (int h = 0; h < HH; h++) {
            float a = 0.f;
            #pragma unroll
            for (int d = 0; d < DD; d++) a += sQ[h*DD + d] * wrow[h*DD + d];
            sKQ[h*EE + t] = a;
        }
    }
    __syncthreads();

    // scores[h][c] = 0.25 * CE[c] . kq[h], mask -> NEG
    for (int idx = t; idx < HH*CC; idx += 128) {
        int h = idx / CC, c = idx % CC;
        float a = 0.f;
        #pragma unroll 8
        for (int e = 0; e < EE; e++) a += sCE[c*EE + e] * sKQ[h*EE + e];
        a *= 0.25f;                    // 1/sqrt(D), D=16
        if (sVcm[c]) a = NEGV;
        sSc[h*CC + c] = a;
    }
    __syncthreads();

    // softmax per head (8 threads, 50 elems each)
    if (t < HH) {
        float mx = -3e38f;
        for (int c = 0; c < CC; c++) mx = fmaxf(mx, sSc[t*CC + c]);
        float sm = 0.f;
        for (int c = 0; c < CC; c++) { float e = expf(sSc[t*CC + c] - mx); sAt[t*CC + c] = e; sm += e; }
        float inv = 1.f / sm;
        for (int c = 0; c < CC; c++) sAt[t*CC + c] *= inv;
    }
    __syncthreads();

    // a_ce[h][e=t] = sum_c attn[h][c] * CE[c][e]
    #pragma unroll
    for (int h = 0; h < HH; h++) {
        float a = 0.f;
        for (int c = 0; c < CC; c++) a += sAt[h*CC + c] * sCE[c*EE + t];
        sAce[h*EE + t] = a;
    }
    __syncthreads();

    // glimpse_flat[j=t] = a_ce[h] . Wvf[:, j]   (h = j/16)
    {
        int h = t / DD;
        float a = 0.f;
        #pragma unroll 8
        for (int e = 0; e < EE; e++) a += sAce[h*EE + e] * g_Wvf[e*EE + t];
        sGl[t] = a;
    }
    __syncthreads();

    // out = glimpse @ Wo
    {
        float a = 0.f;
        #pragma unroll 8
        for (int j = 0; j < EE; j++) a += sGl[j] * Wo[j*EE + t];
        sOut[t] = a;
    }
    __syncthreads();

    // w2[e=t] = Wks[e,:] . out
    {
        const float* wr = Wks + t*EE;
        float a = 0.f;
        #pragma unroll 8
        for (int f = 0; f < EE; f++) a += wr[f] * sOut[f];
        sW2[t] = a;
    }
    __syncthreads();

    // logit[c] = tanh(CE[c].w2 / sqrt(E)) * CLIP, mask -> NEG
    if (t < CC) {
        float a = 0.f;
        #pragma unroll 8
        for (int e = 0; e < EE; e++) a += sCE[t*EE + e] * sW2[e];
        a *= 0.08838834764831845f;     // 1/sqrt(128)
        a = tanhf(a) * 10.f;
        if (sVcm[t]) a = NEGV;
        sLg[t] = a;
    }
    __syncthreads();

    // argmax (first-index tie-break like jnp.argmax) + logsumexp
    if (t == 0) {
        float mx = sLg[0]; int arg = 0;
        for (int c = 1; c < CC; c++) if (sLg[c] > mx) { mx = sLg[c]; arg = c; }
        float sm = 0.f;
        for (int c = 0; c < CC; c++) sm += expf(sLg[c] - mx);
        sMax = mx; sLse = logf(sm); sArg = arg;
    }
    __syncthreads();

    int  guid = sArg;
    bool isn  = isnew[b] != 0;
    float ge  = sCE[guid*EE + t];      // new guidance embedding, dim t

    const size_t OFF1 = (size_t)BB*4*EE;            // guid_embed_out
    const size_t OFF2 = OFF1 + (size_t)BB*EE;       // guid_out
    const size_t OFF3 = OFF2 + BB;                  // clu_prob

    float* ao = out + (size_t)b*4*EE;
    const float* ac = augc + (size_t)b*4*EE;
    ao[t]         = isn ? sUC[t]         : ac[t];           // unvisit_cluster
    ao[EE + t]    = isn ? sCtx[EE + t]   : ac[EE + t];      // current
    ao[2*EE + t]  = isn ? ge             : ac[2*EE + t];    // new_guid_embed
    ao[3*EE + t]  = isn ? sCtx[2*EE + t] : ac[3*EE + t];    // depot

    out[OFF1 + (size_t)b*EE + t] = isn ? ge : gein[b*EE + t];
    if (t == 0) out[OFF2 + b] = (float)(isn ? guid : guid_in[b]);
    if (t < CC) out[OFF3 + (size_t)b*CC + t] = isn ? (sLg[t] - sMax - sLse) : 0.f;
}

// ---------------------------------------------------------------------------
extern "C" void kernel_launch(void* const* d_in, const int* in_sizes, int n_in,
                              void* d_out, int out_size) {
    const float* depot = (const float*)d_in[0];
    const float* CE    = (const float*)d_in[1];
    const float* cur   = (const float*)d_in[2];
    const float* nodes = (const float*)d_in[3];
    const float* augc  = (const float*)d_in[4];
    const float* gein  = (const float*)d_in[5];
    const float* Wq    = (const float*)d_in[6];
    const float* Wk    = (const float*)d_in[7];
    const float* Wv    = (const float*)d_in[8];
    const float* Wks   = (const float*)d_in[9];
    const float* mWq   = (const float*)d_in[10];
    const float* mWk   = (const float*)d_in[11];
    const float* mWv   = (const float*)d_in[12];
    const float* Wo    = (const float*)d_in[13];
    const int* isnew   = (const int*)d_in[14];   // bool -> int32
    const int* mask    = (const int*)d_in[15];   // bool -> int32
    const int* cmask   = (const int*)d_in[16];   // bool -> int32
    const int* vcm     = (const int*)d_in[17];   // bool -> int32
    const int* guid    = (const int*)d_in[18];
    // d_in[19] = step (unused)

    dim3 gr(BB, SPLIT + 2);   // 8 reduce planes + 2 fuse planes (640 rows)
    k_pre<<<gr, 128>>>(nodes, mask, cmask, Wq, Wk, Wv, mWq, mWk, mWv);
    k_main<<<BB, 128>>>(depot, CE, cur, augc, gein, Wks, Wo, isnew, vcm, guid,
                        (float*)d_out);
}

// round 6
// speedup vs baseline: 2.3223x; 1.9109x over previous
#include <cuda_runtime.h>
#include <cstdint>
#include <cmath>

#define BB 512
#define NN 1000
#define CC 50
#define CCP 51              // pitch for transposed cluster tile (odd -> conflict-free)
#define EE 128
#define HH 8
#define DD 16
#define SPLIT 8
#define NPS (NN/SPLIT)
#define NEGV (-1e9f)
#define FUSE_ROWS (6*EE)    // 768 rows of weight prep work

// scratch (no cudaMalloc allowed)
__device__ float g_part[BB*SPLIT*2*EE];   // [b][split][{mask, mask|cmask}][e]
__device__ float g_Wqf [3*EE*EE];         // Wq @ mha_Wq   (384 x 128), [i][t]
__device__ float g_WkfT[EE*EE];           // (Wk @ mha_Wk)^T : [j][e]
__device__ float g_Wvf [EE*EE];           // Wv @ mha_Wv    : [e][j]
__device__ float g_WksT[EE*EE];           // Wks^T          : [f][e]

// ---------------------------------------------------------------------------
// Kernel 1: masked reduction (skip masked rows) + weight prep folded into
// the same grid. grid (BB, SPLIT+2), 128 threads.
// ---------------------------------------------------------------------------
__global__ void __launch_bounds__(128) k_pre(
    const float* __restrict__ nodes,
    const int* __restrict__ mask, const int* __restrict__ cmask,
    const float* __restrict__ Wq, const float* __restrict__ Wk,
    const float* __restrict__ Wv, const float* __restrict__ Wks,
    const float* __restrict__ mWq, const float* __restrict__ mWk,
    const float* __restrict__ mWv)
{
    const int b = blockIdx.x, y = blockIdx.y, t = threadIdx.x;

    if (y >= SPLIT) {
        // ---- weight prep plane ----
        int fr = (y - SPLIT)*BB + b;
        if (fr >= FUSE_ROWS) return;
        if (fr < 3*EE) {
            float a = 0.f;
            #pragma unroll 8
            for (int e = 0; e < EE; e++) a += Wq[fr*EE + e] * mWq[e*EE + t];
            g_Wqf[fr*EE + t] = a;
        } else if (fr < 4*EE) {
            int e0 = fr - 3*EE;              // row of Wkf
            float a = 0.f;
            #pragma unroll 8
            for (int x = 0; x < EE; x++) a += Wk[e0*EE + x] * mWk[x*EE + t];
            g_WkfT[t*EE + e0] = a;           // store transposed
        } else if (fr < 5*EE) {
            int e0 = fr - 4*EE;
            float a = 0.f;
            #pragma unroll 8
            for (int x = 0; x < EE; x++) a += Wv[e0*EE + x] * mWv[x*EE + t];
            g_Wvf[e0*EE + t] = a;
        } else {
            int f = fr - 5*EE;               // WksT[f][t] = Wks[t][f]
            g_WksT[f*EE + t] = Wks[t*EE + f];
        }
        return;
    }

    // ---- reduction plane: rows [y*NPS, (y+1)*NPS) of batch b ----
    __shared__ uint8_t sM[NPS], sC[NPS];
    __shared__ float4  sP0[4][32];
    __shared__ float4  sP1[4][32];

    const int* m  = mask  + b*NN + y*NPS;
    const int* cm = cmask + b*NN + y*NPS;
    if (t < NPS) {
        sM[t] = (uint8_t)(m[t] != 0);
        sC[t] = (uint8_t)(cm[t] != 0);
    }
    __syncthreads();

    const int warp = t >> 5, lane = t & 31;
    const float4* base = (const float4*)(nodes + ((size_t)b*NN + (size_t)y*NPS)*EE);

    float4 a0 = make_float4(0.f,0.f,0.f,0.f);
    float4 a1 = make_float4(0.f,0.f,0.f,0.f);
    for (int r = warp; r < NPS; r += 4) {
        if (!sM[r]) {                        // warp-uniform: skip masked rows
            float4 v = __ldg(base + r*32 + lane);
            a0.x += v.x; a0.y += v.y; a0.z += v.z; a0.w += v.w;
            if (!sC[r]) { a1.x += v.x; a1.y += v.y; a1.z += v.z; a1.w += v.w; }
        }
    }
    sP0[warp][lane] = a0;
    sP1[warp][lane] = a1;
    __syncthreads();

    const float* p0 = (const float*)sP0;
    const float* p1 = (const float*)sP1;
    float s0 = p0[t] + p0[128 + t] + p0[256 + t] + p0[384 + t];
    float s1 = p1[t] + p1[128 + t] + p1[256 + t] + p1[384 + t];
    int idx = (b*SPLIT + y)*2*EE + t;
    g_part[idx]      = s0;
    g_part[idx + EE] = s1;
}

// ---------------------------------------------------------------------------
// Kernel 2: everything else, one block per batch element.
// Cluster tile kept TRANSPOSED in smem: sCET[e*CCP + c] (CCP=51, odd pitch)
// so every access pattern is bank-conflict-free.
// ---------------------------------------------------------------------------
__global__ void __launch_bounds__(128) k_main(
    const float* __restrict__ depot, const float* __restrict__ CE,
    const float* __restrict__ cur,   const float* __restrict__ augc,
    const float* __restrict__ gein,  const float* __restrict__ Wo,
    const int* __restrict__ isnew, const int* __restrict__ vcm_g,
    const int* __restrict__ guid_in, float* __restrict__ out)
{
    int b = blockIdx.x, t = threadIdx.x;
    __shared__ float sCET[EE*CCP];           // transposed cluster embeddings
    __shared__ float sCtx[3*EE];
    __shared__ float sUC[EE];
    __shared__ float sQ[EE];
    __shared__ float sKQ[HH*EE];
    __shared__ float sSc[HH*CC];
    __shared__ float sAt[HH*CC];
    __shared__ float sAce[HH*EE];
    __shared__ float sGl[EE];
    __shared__ float sOut[EE];
    __shared__ float sW2[EE];
    __shared__ float sLg[CC];
    __shared__ int   sVcm[CC];
    __shared__ float sMax, sLse;
    __shared__ int   sArg;

    // load cluster embeddings transposed: global coalesced, smem conflict-free
    {
        const float* src = CE + (size_t)b*CC*EE;
        #pragma unroll
        for (int c = 0; c < CC; c++)
            sCET[t*CCP + c] = src[c*EE + t];
    }

    // combine reduction partials
    float um = 0.f, uc = 0.f;
    #pragma unroll
    for (int s = 0; s < SPLIT; s++) {
        int idx = (b*SPLIT + s)*2*EE + t;
        um += g_part[idx];
        uc += g_part[idx + EE];
    }
    um *= (1.f/NN); uc *= (1.f/NN);
    sCtx[t]        = um;
    sCtx[EE + t]   = cur[b*EE + t];
    sCtx[2*EE + t] = depot[b*EE + t];
    sUC[t] = uc;
    if (t < CC) sVcm[t] = (vcm_g[b*CC + t] != 0);
    __syncthreads();

    // vcm[0] = !all(vcm[1:]) (single writer; consumed after a later sync)
    if (t == 0) {
        int all = 1;
        for (int c = 1; c < CC; c++) all &= (sVcm[c] != 0);
        sVcm[0] = !all;
    }

    // q (head-projected via fused Wqf): 384 MACs/thread, coalesced L2 reads
    {
        float a = 0.f;
        #pragma unroll 8
        for (int i = 0; i < 3*EE; i++) a += sCtx[i] * g_Wqf[i*EE + t];
        sQ[t] = a;
    }
    __syncthreads();

    // kq[h][e=t] = sum_d q[h*16+d] * WkfT[h*16+d][t]   (coalesced)
    {
        #pragma unroll
        for (int h = 0; h < HH; h++) {
            float a = 0.f;
            #pragma unroll
            for (int d = 0; d < DD; d++)
                a += sQ[h*DD + d] * g_WkfT[(h*DD + d)*EE + t];
            sKQ[h*EE + t] = a;
        }
    }
    __syncthreads();

    // scores[h][c] = 0.25 * CE[c] . kq[h], mask -> NEG  (conflict-free LDS)
    for (int idx = t; idx < HH*CC; idx += 128) {
        int h = idx / CC, c = idx % CC;
        float a = 0.f;
        #pragma unroll 8
        for (int e = 0; e < EE; e++) a += sCET[e*CCP + c] * sKQ[h*EE + e];
        a *= 0.25f;                    // 1/sqrt(D), D=16
        if (sVcm[c]) a = NEGV;
        sSc[h*CC + c] = a;
    }
    __syncthreads();

    // softmax per head (8 threads, 50 elems each)
    if (t < HH) {
        float mx = -3e38f;
        for (int c = 0; c < CC; c++) mx = fmaxf(mx, sSc[t*CC + c]);
        float sm = 0.f;
        for (int c = 0; c < CC; c++) { float e = expf(sSc[t*CC + c] - mx); sAt[t*CC + c] = e; sm += e; }
        float inv = 1.f / sm;
        for (int c = 0; c < CC; c++) sAt[t*CC + c] *= inv;
    }
    __syncthreads();

    // a_ce[h][e=t] = sum_c attn[h][c] * CET[t][c]   (conflict-free: odd pitch)
    #pragma unroll
    for (int h = 0; h < HH; h++) {
        float a = 0.f;
        for (int c = 0; c < CC; c++) a += sAt[h*CC + c] * sCET[t*CCP + c];
        sAce[h*EE + t] = a;
    }
    __syncthreads();

    // glimpse_flat[j=t] = a_ce[h] . Wvf[:, j]   (h = j/16)
    {
        int h = t / DD;
        float a = 0.f;
        #pragma unroll 8
        for (int e = 0; e < EE; e++) a += sAce[h*EE + e] * g_Wvf[e*EE + t];
        sGl[t] = a;
    }
    __syncthreads();

    // out = glimpse @ Wo
    {
        float a = 0.f;
        #pragma unroll 8
        for (int j = 0; j < EE; j++) a += sGl[j] * Wo[j*EE + t];
        sOut[t] = a;
    }
    __syncthreads();

    // w2[e=t] = sum_f WksT[f][t] * out[f]   (coalesced)
    {
        float a = 0.f;
        #pragma unroll 8
        for (int f = 0; f < EE; f++) a += g_WksT[f*EE + t] * sOut[f];
        sW2[t] = a;
    }
    __syncthreads();

    // logit[c] = tanh(CE[c].w2 / sqrt(E)) * CLIP, mask -> NEG (conflict-free)
    if (t < CC) {
        float a = 0.f;
        #pragma unroll 8
        for (int e = 0; e < EE; e++) a += sCET[e*CCP + t] * sW2[e];
        a *= 0.08838834764831845f;     // 1/sqrt(128)
        a = tanhf(a) * 10.f;
        if (sVcm[t]) a = NEGV;
        sLg[t] = a;
    }
    __syncthreads();

    // argmax (first-index tie-break like jnp.argmax) + logsumexp
    if (t == 0) {
        float mx = sLg[0]; int arg = 0;
        for (int c = 1; c < CC; c++) if (sLg[c] > mx) { mx = sLg[c]; arg = c; }
        float sm = 0.f;
        for (int c = 0; c < CC; c++) sm += expf(sLg[c] - mx);
        sMax = mx; sLse = logf(sm); sArg = arg;
    }
    __syncthreads();

    int  guid = sArg;
    bool isn  = isnew[b] != 0;
    float ge  = sCET[t*CCP + guid];    // new guidance embedding, dim t

    const size_t OFF1 = (size_t)BB*4*EE;            // guid_embed_out
    const size_t OFF2 = OFF1 + (size_t)BB*EE;       // guid_out
    const size_t OFF3 = OFF2 + BB;                  // clu_prob

    float* ao = out + (size_t)b*4*EE;
    const float* ac = augc + (size_t)b*4*EE;
    ao[t]         = isn ? sUC[t]         : ac[t];           // unvisit_cluster
    ao[EE + t]    = isn ? sCtx[EE + t]   : ac[EE + t];      // current
    ao[2*EE + t]  = isn ? ge             : ac[2*EE + t];    // new_guid_embed
    ao[3*EE + t]  = isn ? sCtx[2*EE + t] : ac[3*EE + t];    // depot

    out[OFF1 + (size_t)b*EE + t] = isn ? ge : gein[b*EE + t];
    if (t == 0) out[OFF2 + b] = (float)(isn ? guid : guid_in[b]);
    if (t < CC) out[OFF3 + (size_t)b*CC + t] = isn ? (sLg[t] - sMax - sLse) : 0.f;
}

// ---------------------------------------------------------------------------
extern "C" void kernel_launch(void* const* d_in, const int* in_sizes, int n_in,
                              void* d_out, int out_size) {
    const float* depot = (const float*)d_in[0];
    const float* CE    = (const float*)d_in[1];
    const float* cur   = (const float*)d_in[2];
    const float* nodes = (const float*)d_in[3];
    const float* augc  = (const float*)d_in[4];
    const float* gein  = (const float*)d_in[5];
    const float* Wq    = (const float*)d_in[6];
    const float* Wk    = (const float*)d_in[7];
    const float* Wv    = (const float*)d_in[8];
    const float* Wks   = (const float*)d_in[9];
    const float* mWq   = (const float*)d_in[10];
    const float* mWk   = (const float*)d_in[11];
    const float* mWv   = (const float*)d_in[12];
    const float* Wo    = (const float*)d_in[13];
    const int* isnew   = (const int*)d_in[14];   // bool -> int32
    const int* mask    = (const int*)d_in[15];   // bool -> int32
    const int* cmask   = (const int*)d_in[16];   // bool -> int32
    const int* vcm     = (const int*)d_in[17];   // bool -> int32
    const int* guid    = (const int*)d_in[18];
    // d_in[19] = step (unused)

    dim3 gr(BB, SPLIT + 2);   // 8 reduce planes + 2 prep planes (768 rows)
    k_pre<<<gr, 128>>>(nodes, mask, cmask, Wq, Wk, Wv, Wks, mWq, mWk, mWv);
    k_main<<<BB, 128>>>(depot, CE, cur, augc, gein, Wo, isnew, vcm, guid,
                        (float*)d_out);
}

// round 7
// speedup vs baseline: 2.7190x; 1.1708x over previous
#include <cuda_runtime.h>
#include <cstdint>
#include <cmath>

#define BB 512
#define NN 1000
#define CC 50
#define CCP 51              // pitch for transposed cluster tile (odd -> conflict-free)
#define EE 128
#define HH 8
#define DD 16
#define SPLIT 8
#define NPS (NN/SPLIT)
#define NEGV (-1e9f)
#define FUSE_ROWS (6*EE)    // 768 rows of weight prep work

// scratch (no cudaMalloc allowed)
__device__ float g_part[BB*SPLIT*2*EE];   // [b][split][{mask, mask|cmask}][e]
__device__ float g_Wqf [3*EE*EE];         // Wq @ mha_Wq   (384 x 128), [i][t]
__device__ float g_WkfT[EE*EE];           // (Wk @ mha_Wk)^T : [j][e]
__device__ float g_Wvf [EE*EE];           // Wv @ mha_Wv    : [e][j]
__device__ float g_WksT[EE*EE];           // Wks^T          : [f][e]

// ---------------------------------------------------------------------------
// Kernel 1: masked reduction (skip masked rows) + weight prep folded in.
// grid (BB, SPLIT+2), 128 threads.   (unchanged: already at roofline)
// ---------------------------------------------------------------------------
__global__ void __launch_bounds__(128) k_pre(
    const float* __restrict__ nodes,
    const int* __restrict__ mask, const int* __restrict__ cmask,
    const float* __restrict__ Wq, const float* __restrict__ Wk,
    const float* __restrict__ Wv, const float* __restrict__ Wks,
    const float* __restrict__ mWq, const float* __restrict__ mWk,
    const float* __restrict__ mWv)
{
    const int b = blockIdx.x, y = blockIdx.y, t = threadIdx.x;

    if (y >= SPLIT) {
        int fr = (y - SPLIT)*BB + b;
        if (fr >= FUSE_ROWS) return;
        if (fr < 3*EE) {
            float a = 0.f;
            #pragma unroll 8
            for (int e = 0; e < EE; e++) a += Wq[fr*EE + e] * mWq[e*EE + t];
            g_Wqf[fr*EE + t] = a;
        } else if (fr < 4*EE) {
            int e0 = fr - 3*EE;
            float a = 0.f;
            #pragma unroll 8
            for (int x = 0; x < EE; x++) a += Wk[e0*EE + x] * mWk[x*EE + t];
            g_WkfT[t*EE + e0] = a;           // store transposed
        } else if (fr < 5*EE) {
            int e0 = fr - 4*EE;
            float a = 0.f;
            #pragma unroll 8
            for (int x = 0; x < EE; x++) a += Wv[e0*EE + x] * mWv[x*EE + t];
            g_Wvf[e0*EE + t] = a;
        } else {
            int f = fr - 5*EE;
            g_WksT[f*EE + t] = Wks[t*EE + f];
        }
        return;
    }

    __shared__ uint8_t sM[NPS], sC[NPS];
    __shared__ float4  sP0[4][32];
    __shared__ float4  sP1[4][32];

    const int* m  = mask  + b*NN + y*NPS;
    const int* cm = cmask + b*NN + y*NPS;
    if (t < NPS) {
        sM[t] = (uint8_t)(m[t] != 0);
        sC[t] = (uint8_t)(cm[t] != 0);
    }
    __syncthreads();

    const int warp = t >> 5, lane = t & 31;
    const float4* base = (const float4*)(nodes + ((size_t)b*NN + (size_t)y*NPS)*EE);

    float4 a0 = make_float4(0.f,0.f,0.f,0.f);
    float4 a1 = make_float4(0.f,0.f,0.f,0.f);
    for (int r = warp; r < NPS; r += 4) {
        if (!sM[r]) {                        // warp-uniform: skip masked rows
            float4 v = __ldg(base + r*32 + lane);
            a0.x += v.x; a0.y += v.y; a0.z += v.z; a0.w += v.w;
            if (!sC[r]) { a1.x += v.x; a1.y += v.y; a1.z += v.z; a1.w += v.w; }
        }
    }
    sP0[warp][lane] = a0;
    sP1[warp][lane] = a1;
    __syncthreads();

    const float* p0 = (const float*)sP0;
    const float* p1 = (const float*)sP1;
    float s0 = p0[t] + p0[128 + t] + p0[256 + t] + p0[384 + t];
    float s1 = p1[t] + p1[128 + t] + p1[256 + t] + p1[384 + t];
    int idx = (b*SPLIT + y)*2*EE + t;
    g_part[idx]      = s0;
    g_part[idx + EE] = s1;
}

// ---------------------------------------------------------------------------
// Kernel 2: 256 threads/block, split-K stages, 4-way accumulators,
// warp-parallel softmax + warp-shfl argmax/LSE.
// ---------------------------------------------------------------------------
__global__ void __launch_bounds__(256) k_main(
    const float* __restrict__ depot, const float* __restrict__ CE,
    const float* __restrict__ cur,   const float* __restrict__ augc,
    const float* __restrict__ gein,  const float* __restrict__ Wo,
    const int* __restrict__ isnew, const int* __restrict__ vcm_g,
    const int* __restrict__ guid_in, float* __restrict__ out)
{
    const int b = blockIdx.x, t = threadIdx.x;
    const int t2 = t & 127, half = t >> 7;
    const int warp = t >> 5, lane = t & 31;

    __shared__ float sCET[EE*CCP];     // transposed cluster embeddings
    __shared__ float sCtx[3*EE];
    __shared__ float sUC[EE];
    __shared__ float sP2[2][EE];       // split-K partials (reused per stage)
    __shared__ float sQ[EE];
    __shared__ float sKQ[HH*EE];
    __shared__ float sSc[HH*CC];
    __shared__ float sAt[HH*CC];
    __shared__ float sAce[HH*EE];
    __shared__ float sGl[EE];
    __shared__ float sOut[EE];
    __shared__ float sW2[EE];
    __shared__ float sLgP[4][CC];
    __shared__ float sLg[CC];
    __shared__ int   sVcm[CC];
    __shared__ float sMax, sLse;
    __shared__ int   sArg;

    // ---- load cluster embeddings transposed; half owns 25 c's, e = t2 ----
    {
        const float* src = CE + (size_t)b*CC*EE;
        #pragma unroll
        for (int cc = 0; cc < 25; cc++) {
            int c = half*25 + cc;
            sCET[t2*CCP + c] = src[c*EE + t2];   // global coalesced per half
        }
    }

    // ---- combine reduction partials: half 0 -> um, half 1 -> uc ----
    {
        float a = 0.f;
        #pragma unroll
        for (int s = 0; s < SPLIT; s++)
            a += g_part[(b*SPLIT + s)*2*EE + half*EE + t2];
        a *= (1.f/NN);
        if (half == 0) sCtx[t2] = a; else sUC[t2] = a;
    }
    if (half == 0) sCtx[EE + t2]   = cur[b*EE + t2];
    else           sCtx[2*EE + t2] = depot[b*EE + t2];
    if (t < CC) sVcm[t] = (vcm_g[b*CC + t] != 0);
    __syncthreads();

    if (t == 0) {                      // vcm[0] = !all(vcm[1:])
        int all = 1;
        for (int c = 1; c < CC; c++) all &= (sVcm[c] != 0);
        sVcm[0] = !all;
    }

    // ---- q projection, split-K over halves (192 MACs each, 4 accs) ----
    {
        const int i0 = half*192;
        float a0=0.f,a1=0.f,a2=0.f,a3=0.f;
        #pragma unroll 4
        for (int i = 0; i < 192; i += 4) {
            a0 += sCtx[i0+i  ] * g_Wqf[(i0+i  )*EE + t2];
            a1 += sCtx[i0+i+1] * g_Wqf[(i0+i+1)*EE + t2];
            a2 += sCtx[i0+i+2] * g_Wqf[(i0+i+2)*EE + t2];
            a3 += sCtx[i0+i+3] * g_Wqf[(i0+i+3)*EE + t2];
        }
        sP2[half][t2] = (a0+a1)+(a2+a3);
    }
    __syncthreads();
    if (half == 0) sQ[t2] = sP2[0][t2] + sP2[1][t2];
    __syncthreads();

    // ---- kq[h][e]: 1024 outputs over 256 threads (4 each), 16 MACs ----
    #pragma unroll
    for (int k = 0; k < 4; k++) {
        int idx = t + 256*k;
        int h = idx >> 7, e = idx & 127;
        float a0=0.f,a1=0.f;
        #pragma unroll
        for (int d = 0; d < DD; d += 2) {
            a0 += sQ[h*DD + d  ] * g_WkfT[(h*DD + d  )*EE + e];
            a1 += sQ[h*DD + d+1] * g_WkfT[(h*DD + d+1)*EE + e];
        }
        sKQ[h*EE + e] = a0 + a1;
    }
    __syncthreads();

    // ---- scores: 400 outputs, 128 MACs, 4 accs ----
    for (int idx = t; idx < HH*CC; idx += 256) {
        int h = idx / CC, c = idx % CC;
        float a0=0.f,a1=0.f,a2=0.f,a3=0.f;
        #pragma unroll 4
        for (int e = 0; e < EE; e += 4) {
            a0 += sCET[(e  )*CCP + c] * sKQ[h*EE + e  ];
            a1 += sCET[(e+1)*CCP + c] * sKQ[h*EE + e+1];
            a2 += sCET[(e+2)*CCP + c] * sKQ[h*EE + e+2];
            a3 += sCET[(e+3)*CCP + c] * sKQ[h*EE + e+3];
        }
        float a = ((a0+a1)+(a2+a3)) * 0.25f;   // 1/sqrt(16)
        if (sVcm[c]) a = NEGV;
        sSc[h*CC + c] = a;
    }
    __syncthreads();

    // ---- softmax: warp h owns head h; lanes cover c=lane and c=lane+32 ----
    {
        int h = warp;                    // 8 warps, 8 heads
        float v0 = sSc[h*CC + lane];
        float v1 = (lane < CC-32) ? sSc[h*CC + lane + 32] : -3e38f;
        float mx = fmaxf(v0, v1);
        #pragma unroll
        for (int o = 16; o > 0; o >>= 1)
            mx = fmaxf(mx, __shfl_xor_sync(0xffffffffu, mx, o));
        float e0 = expf(v0 - mx);
        float e1 = (lane < CC-32) ? expf(v1 - mx) : 0.f;
        float sm = e0 + e1;
        #pragma unroll
        for (int o = 16; o > 0; o >>= 1)
            sm += __shfl_xor_sync(0xffffffffu, sm, o);
        float inv = 1.f / sm;
        sAt[h*CC + lane] = e0 * inv;
        if (lane < CC-32) sAt[h*CC + lane + 32] = e1 * inv;
    }
    __syncthreads();

    // ---- a_ce[h][e]: 1024 outputs over 256 threads, 50 MACs, 2 accs ----
    #pragma unroll
    for (int k = 0; k < 4; k++) {
        int idx = t + 256*k;
        int h = idx >> 7, e = idx & 127;
        float a0=0.f,a1=0.f;
        #pragma unroll 5
        for (int c = 0; c < CC; c += 2) {
            a0 += sAt[h*CC + c  ] * sCET[e*CCP + c  ];
            a1 += sAt[h*CC + c+1] * sCET[e*CCP + c+1];
        }
        sAce[h*EE + e] = a0 + a1;
    }
    __syncthreads();

    // ---- glimpse[j=t2]: 128-MAC split-K over halves (h = j/16) ----
    {
        int h = t2 / DD;
        const int e0 = half*64;
        float a0=0.f,a1=0.f,a2=0.f,a3=0.f;
        #pragma unroll 4
        for (int e = 0; e < 64; e += 4) {
            a0 += sAce[h*EE + e0+e  ] * g_Wvf[(e0+e  )*EE + t2];
            a1 += sAce[h*EE + e0+e+1] * g_Wvf[(e0+e+1)*EE + t2];
            a2 += sAce[h*EE + e0+e+2] * g_Wvf[(e0+e+2)*EE + t2];
            a3 += sAce[h*EE + e0+e+3] * g_Wvf[(e0+e+3)*EE + t2];
        }
        sP2[half][t2] = (a0+a1)+(a2+a3);
    }
    __syncthreads();
    if (half == 0) sGl[t2] = sP2[0][t2] + sP2[1][t2];
    __syncthreads();

    // ---- out = glimpse @ Wo: split-K over halves ----
    {
        const int j0 = half*64;
        float a0=0.f,a1=0.f,a2=0.f,a3=0.f;
        #pragma unroll 4
        for (int j = 0; j < 64; j += 4) {
            a0 += sGl[j0+j  ] * Wo[(j0+j  )*EE + t2];
            a1 += sGl[j0+j+1] * Wo[(j0+j+1)*EE + t2];
            a2 += sGl[j0+j+2] * Wo[(j0+j+2)*EE + t2];
            a3 += sGl[j0+j+3] * Wo[(j0+j+3)*EE + t2];
        }
        sP2[half][t2] = (a0+a1)+(a2+a3);
    }
    __syncthreads();
    if (half == 0) sOut[t2] = sP2[0][t2] + sP2[1][t2];
    __syncthreads();

    // ---- w2[e=t2]: split-K over halves ----
    {
        const int f0 = half*64;
        float a0=0.f,a1=0.f,a2=0.f,a3=0.f;
        #pragma unroll 4
        for (int f = 0; f < 64; f += 4) {
            a0 += g_WksT[(f0+f  )*EE + t2] * sOut[f0+f  ];
            a1 += g_WksT[(f0+f+1)*EE + t2] * sOut[f0+f+1];
            a2 += g_WksT[(f0+f+2)*EE + t2] * sOut[f0+f+2];
            a3 += g_WksT[(f0+f+3)*EE + t2] * sOut[f0+f+3];
        }
        sP2[half][t2] = (a0+a1)+(a2+a3);
    }
    __syncthreads();
    if (half == 0) sW2[t2] = sP2[0][t2] + sP2[1][t2];
    __syncthreads();

    // ---- logit[c]: 50 outputs, split over 4 quarters of e (32 MACs each) ----
    {
        int c = t & 63, q4 = t >> 6;
        if (c < CC) {
            const int e0 = q4*32;
            float a0=0.f,a1=0.f;
            #pragma unroll 4
            for (int e = 0; e < 32; e += 2) {
                a0 += sCET[(e0+e  )*CCP + c] * sW2[e0+e  ];
                a1 += sCET[(e0+e+1)*CCP + c] * sW2[e0+e+1];
            }
            sLgP[q4][c] = a0 + a1;
        }
    }
    __syncthreads();
    if (t < CC) {
        float a = (sLgP[0][t] + sLgP[1][t]) + (sLgP[2][t] + sLgP[3][t]);
        a *= 0.08838834764831845f;     // 1/sqrt(128)
        a = tanhf(a) * 10.f;
        if (sVcm[t]) a = NEGV;
        sLg[t] = a;
    }
    __syncthreads();

    // ---- argmax (first-index ties) + logsumexp, warp 0 via shfl ----
    if (warp == 0) {
        float v0 = sLg[lane];
        float v1 = (lane < CC-32) ? sLg[lane + 32] : -3e38f;
        // pairwise: strictly greater wins (keeps lower index on ties)
        float v = v0; int ix = lane;
        if (v1 > v) { v = v1; ix = lane + 32; }
        #pragma unroll
        for (int o = 16; o > 0; o >>= 1) {
            float ov = __shfl_xor_sync(0xffffffffu, v, o);
            int   oi = __shfl_xor_sync(0xffffffffu, ix, o);
            if (ov > v || (ov == v && oi < ix)) { v = ov; ix = oi; }
        }
        float mx = v;
        float sm = expf(v0 - mx) + ((lane < CC-32) ? expf(v1 - mx) : 0.f);
        #pragma unroll
        for (int o = 16; o > 0; o >>= 1)
            sm += __shfl_xor_sync(0xffffffffu, sm, o);
        if (lane == 0) { sMax = mx; sLse = logf(sm); sArg = ix; }
    }
    __syncthreads();

    const int  guid = sArg;
    const bool isn  = isnew[b] != 0;
    const float ge  = sCET[t2*CCP + guid];

    const size_t OFF1 = (size_t)BB*4*EE;            // guid_embed_out
    const size_t OFF2 = OFF1 + (size_t)BB*EE;       // guid_out
    const size_t OFF3 = OFF2 + BB;                  // clu_prob

    float* ao = out + (size_t)b*4*EE;
    const float* ac = augc + (size_t)b*4*EE;
    if (half == 0) {
        ao[t2]        = isn ? sUC[t2]         : ac[t2];
        ao[2*EE + t2] = isn ? ge              : ac[2*EE + t2];
        out[OFF1 + (size_t)b*EE + t2] = isn ? ge : gein[b*EE + t2];
    } else {
        ao[EE + t2]   = isn ? sCtx[EE + t2]   : ac[EE + t2];
        ao[3*EE + t2] = isn ? sCtx[2*EE + t2] : ac[3*EE + t2];
    }
    if (t == 0) out[OFF2 + b] = (float)(isn ? guid : guid_in[b]);
    if (t < CC) out[OFF3 + (size_t)b*CC + t] = isn ? (sLg[t] - sMax - sLse) : 0.f;
}

// ---------------------------------------------------------------------------
extern "C" void kernel_launch(void* const* d_in, const int* in_sizes, int n_in,
                              void* d_out, int out_size) {
    const float* depot = (const float*)d_in[0];
    const float* CE    = (const float*)d_in[1];
    const float* cur   = (const float*)d_in[2];
    const float* nodes = (const float*)d_in[3];
    const float* augc  = (const float*)d_in[4];
    const float* gein  = (const float*)d_in[5];
    const float* Wq    = (const float*)d_in[6];
    const float* Wk    = (const float*)d_in[7];
    const float* Wv    = (const float*)d_in[8];
    const float* Wks   = (const float*)d_in[9];
    const float* mWq   = (const float*)d_in[10];
    const float* mWk   = (const float*)d_in[11];
    const float* mWv   = (const float*)d_in[12];
    const float* Wo    = (const float*)d_in[13];
    const int* isnew   = (const int*)d_in[14];   // bool -> int32
    const int* mask    = (const int*)d_in[15];   // bool -> int32
    const int* cmask   = (const int*)d_in[16];   // bool -> int32
    const int* vcm     = (const int*)d_in[17];   // bool -> int32
    const int* guid    = (const int*)d_in[18];
    // d_in[19] = step (unused)

    dim3 gr(BB, SPLIT + 2);   // 8 reduce planes + 2 prep planes
    k_pre<<<gr, 128>>>(nodes, mask, cmask, Wq, Wk, Wv, Wks, mWq, mWk, mWv);
    k_main<<<BB, 256>>>(depot, CE, cur, augc, gein, Wo, isnew, vcm, guid,
                        (float*)d_out);
}